// round 3
// baseline (speedup 1.0000x reference)
#include <cuda_runtime.h>
#include <cstdint>
#include <math.h>

#define N_NODES 100000
#define N_EDGES 1600000
#define IN_DIM 256
#define HID 64
#define ALPHA 0.1f
#define EOSF 1e-10f
#define BIASF 1e-4f

// output layout: [w_lp_norm (E+N)] [w_hp_norm (E+N)] [weights_lp (E)] [weights_hp (E)]
#define OFF_LPN 0
#define OFF_HPN (N_EDGES + N_NODES)
#define OFF_WLP (2 * (N_EDGES + N_NODES))
#define OFF_WHP (2 * (N_EDGES + N_NODES) + N_EDGES)

// fixed-point packed degree accumulator: count at bit 44, sum(wlp)*2^32 in low 44 bits
#define CNT_SHIFT 44
#define SUM_MASK ((1ULL << CNT_SHIFT) - 1ULL)
#define SUM_SCALE 4294967296.0f           // 2^32
#define SUM_INV (1.0f / 4294967296.0f)

// scratch (no allocations allowed)
__device__ float g_q[N_NODES];
__device__ unsigned long long g_acc_out[N_NODES];
__device__ unsigned long long g_acc_in[N_NODES];
__device__ __align__(16) float2 g_ro[N_NODES];   // {rsqrt(deg_lo_out), rsqrt(deg_ho_out)}
__device__ __align__(16) float2 g_ri[N_NODES];   // {rsqrt(deg_lo_in),  rsqrt(deg_ho_in)}
__device__ __align__(16) int g_src[N_EDGES];
__device__ __align__(16) int g_dst[N_EDGES];
__device__ int g_is64;

// ---------------------------------------------------------------------------
// packed f32x2 helpers (B300: fma.rn.f32x2 doubles FFMA throughput)
// ---------------------------------------------------------------------------
__device__ __forceinline__ unsigned long long pack2(float lo, float hi) {
    unsigned long long r;
    asm("mov.b64 %0, {%1, %2};" : "=l"(r) : "f"(lo), "f"(hi));
    return r;
}
__device__ __forceinline__ void fma2(unsigned long long& d, unsigned long long a,
                                     unsigned long long b) {
    asm("fma.rn.f32x2 %0, %1, %2, %0;" : "+l"(d) : "l"(a), "l"(b));
}
__device__ __forceinline__ void unpack2(unsigned long long v, float& lo, float& hi) {
    asm("mov.b64 {%0, %1}, %2;" : "=f"(lo), "=f"(hi) : "l"(v));
}

// ---------------------------------------------------------------------------
// Detect whether edges are int64 (odd 32-bit words all zero) or int32.
// ---------------------------------------------------------------------------
__global__ void detect_kernel(const unsigned int* __restrict__ w) {
    if (threadIdx.x == 0) {
        bool z = true;
#pragma unroll
        for (int i = 1; i < 16; i += 2) z = z && (w[i] == 0u);
        g_is64 = z ? 1 : 0;
    }
}

// ---------------------------------------------------------------------------
// Fused node embedding:  q[n] = sum_j relu(feat[n,:] @ Wemb[:,j] + bemb[j]) * wc[j]
// 128x64 tile, BK=32, 8(M)x4(N) per thread via fma.rn.f32x2, register
// double-buffered global loads. Also zeroes the degree accumulators.
// ---------------------------------------------------------------------------
__global__ __launch_bounds__(256, 2) void embed_kernel(
    const float* __restrict__ feat, const float* __restrict__ Wemb,
    const float* __restrict__ bemb, const float* __restrict__ Wedge) {
    constexpr int BM = 128, BK = 32, LDA = BM + 2;
    __shared__ __align__(16) float As[BK][LDA];   // transposed: As[k][m]
    __shared__ __align__(16) float Bs[BK][HID];

    const int tid = threadIdx.x;
    const int tx = tid & 15;   // hidden group: 4 cols each
    const int ty = tid >> 4;   // node group: 8 rows each
    const int row0 = blockIdx.x * BM;

    // zero packed degree accumulators for this block's nodes
    if (tid < BM) {
        int n = row0 + tid;
        if (n < N_NODES) { g_acc_out[n] = 0ull; g_acc_in[n] = 0ull; }
    }

    // per-thread load coordinates
    int am[4], ak4[4];
    const float* aptr[4];
    bool aval[4];
#pragma unroll
    for (int l = 0; l < 4; l++) {
        int idx = tid + l * 256;
        am[l] = idx >> 3;          // node within tile
        ak4[l] = idx & 7;          // float4 within k-tile
        int node = row0 + am[l];
        aval[l] = node < N_NODES;
        aptr[l] = feat + (size_t)(aval[l] ? node : 0) * IN_DIM + ak4[l] * 4;
    }
    int br[2], bc[2];
#pragma unroll
    for (int l = 0; l < 2; l++) {
        int idx = tid + l * 256;
        br[l] = idx >> 4;
        bc[l] = idx & 15;
    }

    unsigned long long acc2[4][4];
#pragma unroll
    for (int p = 0; p < 4; p++)
#pragma unroll
        for (int j = 0; j < 4; j++) acc2[p][j] = 0ull;

    float4 ra[4], rb[2];
    // prologue loads (k0 = 0)
#pragma unroll
    for (int l = 0; l < 4; l++)
        ra[l] = aval[l] ? *(const float4*)(aptr[l]) : make_float4(0.f, 0.f, 0.f, 0.f);
#pragma unroll
    for (int l = 0; l < 2; l++)
        rb[l] = *(const float4*)&Wemb[(size_t)br[l] * HID + bc[l] * 4];

    constexpr int NT = IN_DIM / BK;  // 8
#pragma unroll 1
    for (int t = 0; t < NT; t++) {
        // stage registers -> smem
#pragma unroll
        for (int l = 0; l < 4; l++) {
            As[ak4[l] * 4 + 0][am[l]] = ra[l].x;
            As[ak4[l] * 4 + 1][am[l]] = ra[l].y;
            As[ak4[l] * 4 + 2][am[l]] = ra[l].z;
            As[ak4[l] * 4 + 3][am[l]] = ra[l].w;
        }
#pragma unroll
        for (int l = 0; l < 2; l++) *(float4*)&Bs[br[l]][bc[l] * 4] = rb[l];
        __syncthreads();

        // issue next tile's loads (overlap with compute below)
        if (t + 1 < NT) {
            int k0 = (t + 1) * BK;
#pragma unroll
            for (int l = 0; l < 4; l++)
                ra[l] = aval[l] ? *(const float4*)(aptr[l] + k0)
                                : make_float4(0.f, 0.f, 0.f, 0.f);
#pragma unroll
            for (int l = 0; l < 2; l++)
                rb[l] = *(const float4*)&Wemb[(size_t)(k0 + br[l]) * HID + bc[l] * 4];
        }

#pragma unroll
        for (int kk = 0; kk < BK; kk++) {
            unsigned long long a2[4];
#pragma unroll
            for (int p = 0; p < 4; p++)
                a2[p] = *(const unsigned long long*)&As[kk][ty * 8 + p * 2];
            float4 bv = *(const float4*)&Bs[kk][tx * 4];
            unsigned long long b2[4];
            b2[0] = pack2(bv.x, bv.x);
            b2[1] = pack2(bv.y, bv.y);
            b2[2] = pack2(bv.z, bv.z);
            b2[3] = pack2(bv.w, bv.w);
#pragma unroll
            for (int p = 0; p < 4; p++)
#pragma unroll
                for (int j = 0; j < 4; j++) fma2(acc2[p][j], a2[p], b2[j]);
        }
        __syncthreads();
    }

    // epilogue: bias + relu + dot with wc, reduce across 16 tx lanes
    float bb[4], wc[4];
#pragma unroll
    for (int j = 0; j < 4; j++) {
        int n = tx * 4 + j;
        bb[j] = bemb[n];
        wc[j] = Wedge[n] + Wedge[HID + n];
    }
#pragma unroll
    for (int p = 0; p < 4; p++) {
        float alo[4], ahi[4];
#pragma unroll
        for (int j = 0; j < 4; j++) unpack2(acc2[p][j], alo[j], ahi[j]);
#pragma unroll
        for (int half = 0; half < 2; half++) {
            float s = 0.f;
#pragma unroll
            for (int j = 0; j < 4; j++) {
                float h = (half ? ahi[j] : alo[j]) + bb[j];
                h = fmaxf(h, 0.f);
                s = fmaf(h, wc[j], s);
            }
#pragma unroll
            for (int off = 1; off < 16; off <<= 1)
                s += __shfl_xor_sync(0xffffffffu, s, off, 16);
            if (tx == 0) {
                int node = row0 + ty * 8 + p * 2 + half;
                if (node < N_NODES) g_q[node] = s;
            }
        }
    }
}

// ---------------------------------------------------------------------------
// Edge pass 1 (2 edges/thread): gumbel-sigmoid weights, int32 edge scratch,
// ONE packed 64-bit atomic per endpoint (count + fixed-point sum of wlp).
// ---------------------------------------------------------------------------
__device__ __forceinline__ float edge_w(float q_s, float q_d, float u, float be) {
    float raw = 0.5f * (q_s + q_d) + be;
    float eps = fmaf(2.0f * BIASF - 1.0f, u, 1.0f - BIASF);
    float gate = logf(eps) - log1pf(-eps);
    float x = gate + raw;  // TEMP = 1
    return 1.0f / (1.0f + expf(-x));
}

__global__ __launch_bounds__(256) void edge_weights_kernel(
    const void* __restrict__ edges, const float* __restrict__ noise,
    const float* __restrict__ b_edge_p, float* __restrict__ out) {
    int t = blockIdx.x * blockDim.x + threadIdx.x;
    if (t * 2 >= N_EDGES) return;

    int s0, s1, d0, d1;
    if (g_is64) {
        longlong2 sv = ((const longlong2*)edges)[t];
        longlong2 dv = ((const longlong2*)((const long long*)edges + N_EDGES))[t];
        s0 = (int)sv.x; s1 = (int)sv.y; d0 = (int)dv.x; d1 = (int)dv.y;
    } else {
        int2 sv = ((const int2*)edges)[t];
        int2 dv = ((const int2*)((const int*)edges + N_EDGES))[t];
        s0 = sv.x; s1 = sv.y; d0 = dv.x; d1 = dv.y;
    }
    ((int2*)g_src)[t] = make_int2(s0, s1);
    ((int2*)g_dst)[t] = make_int2(d0, d1);

    float2 u = ((const float2*)noise)[t];
    float be = *b_edge_p;
    float w0 = edge_w(g_q[s0], g_q[d0], u.x, be);
    float w1 = edge_w(g_q[s1], g_q[d1], u.y, be);

    ((float2*)(out + OFF_WLP))[t] = make_float2(w0, w1);
    ((float2*)(out + OFF_WHP))[t] = make_float2(1.0f - w0, 1.0f - w1);

    unsigned long long e0 = (1ULL << CNT_SHIFT) | (unsigned long long)(w0 * SUM_SCALE);
    unsigned long long e1 = (1ULL << CNT_SHIFT) | (unsigned long long)(w1 * SUM_SCALE);
    atomicAdd(&g_acc_out[s0], e0);
    atomicAdd(&g_acc_in[d0], e0);
    atomicAdd(&g_acc_out[s1], e1);
    atomicAdd(&g_acc_in[d1], e1);
}

// ---------------------------------------------------------------------------
// Node pass: decode packed degrees, precompute rsqrt factors, self-loop outputs
// ---------------------------------------------------------------------------
__global__ __launch_bounds__(256) void node_kernel(float* __restrict__ out) {
    int n = blockIdx.x * blockDim.x + threadIdx.x;
    if (n >= N_NODES) return;
    unsigned long long vo = g_acc_out[n], vi = g_acc_in[n];
    float co = (float)(vo >> CNT_SHIFT);
    float So = (float)(vo & SUM_MASK) * SUM_INV;
    float ci = (float)(vi >> CNT_SHIFT);
    float Si = (float)(vi & SUM_MASK) * SUM_INV;
    // deg = 1 (self loop) + sum over incident edges (EOS terms vanish in fp32)
    float2 ro = make_float2(rsqrtf(1.0f + So), rsqrtf(1.0f + co - So));
    float2 ri = make_float2(rsqrtf(1.0f + Si), rsqrtf(1.0f + ci - Si));
    g_ro[n] = ro;
    g_ri[n] = ri;
    out[OFF_LPN + N_EDGES + n] = (1.0f + EOSF) * ro.x * ri.x;
    out[OFF_HPN + N_EDGES + n] = 1.0f;  // hp self-loop forced to 1
}

// ---------------------------------------------------------------------------
// Edge pass 2 (2 edges/thread): normalize with precomputed float2 factors
// ---------------------------------------------------------------------------
__global__ __launch_bounds__(256) void edge_norm_kernel(float* __restrict__ out) {
    int t = blockIdx.x * blockDim.x + threadIdx.x;
    if (t * 2 >= N_EDGES) return;
    int2 s = ((const int2*)g_src)[t];
    int2 d = ((const int2*)g_dst)[t];
    float2 wl = ((const float2*)(out + OFF_WLP))[t];
    float2 wh = ((const float2*)(out + OFF_WHP))[t];
    float2 ro0 = g_ro[s.x], ro1 = g_ro[s.y];
    float2 ri0 = g_ri[d.x], ri1 = g_ri[d.y];
    ((float2*)(out + OFF_LPN))[t] =
        make_float2((wl.x + EOSF) * ro0.x * ri0.x, (wl.y + EOSF) * ro1.x * ri1.x);
    ((float2*)(out + OFF_HPN))[t] =
        make_float2(-ALPHA * (wh.x + EOSF) * ro0.y * ri0.y,
                    -ALPHA * (wh.y + EOSF) * ro1.y * ri1.y);
}

// ---------------------------------------------------------------------------
extern "C" void kernel_launch(void* const* d_in, const int* in_sizes, int n_in,
                              void* d_out, int out_size) {
    const float* features = (const float*)d_in[0];
    const void*  edges    = d_in[1];
    const float* noise    = (const float*)d_in[2];
    const float* Wemb     = (const float*)d_in[3];
    const float* bemb     = (const float*)d_in[4];
    const float* Wedge    = (const float*)d_in[5];
    const float* bedge    = (const float*)d_in[6];
    float* out = (float*)d_out;

    const int ET = N_EDGES / 2;  // 2 edges per thread
    detect_kernel<<<1, 32>>>((const unsigned int*)edges);
    embed_kernel<<<(N_NODES + 127) / 128, 256>>>(features, Wemb, bemb, Wedge);
    edge_weights_kernel<<<(ET + 255) / 256, 256>>>(edges, noise, bedge, out);
    node_kernel<<<(N_NODES + 255) / 256, 256>>>(out);
    edge_norm_kernel<<<(ET + 255) / 256, 256>>>(out);
}

// round 4
// speedup vs baseline: 1.0025x; 1.0025x over previous
#include <cuda_runtime.h>
#include <cstdint>
#include <math.h>

#define N_NODES 100000
#define N_EDGES 1600000
#define IN_DIM 256
#define HID 64
#define ALPHA 0.1f
#define EOSF 1e-10f
#define BIASF 1e-4f

// output layout: [w_lp_norm (E+N)] [w_hp_norm (E+N)] [weights_lp (E)] [weights_hp (E)]
#define OFF_LPN 0
#define OFF_HPN (N_EDGES + N_NODES)
#define OFF_WLP (2 * (N_EDGES + N_NODES))
#define OFF_WHP (2 * (N_EDGES + N_NODES) + N_EDGES)

// fixed-point packed degree accumulator: count at bit 44, sum(wlp)*2^32 in low 44 bits
#define CNT_SHIFT 44
#define SUM_MASK ((1ULL << CNT_SHIFT) - 1ULL)
#define SUM_SCALE 4294967296.0f           // 2^32
#define SUM_INV (1.0f / 4294967296.0f)

// scratch (no allocations allowed)
__device__ float g_q[N_NODES];
__device__ unsigned long long g_acc_out[N_NODES];
__device__ unsigned long long g_acc_in[N_NODES];
__device__ __align__(16) float2 g_ro[N_NODES];   // {rsqrt(deg_lo_out), rsqrt(deg_ho_out)}
__device__ __align__(16) float2 g_ri[N_NODES];   // {rsqrt(deg_lo_in),  rsqrt(deg_ho_in)}
__device__ __align__(16) int g_src[N_EDGES];
__device__ __align__(16) int g_dst[N_EDGES];
__device__ int g_is64;

// ---------------------------------------------------------------------------
// packed f32x2 helpers (B300: fma.rn.f32x2 doubles FFMA throughput)
// ---------------------------------------------------------------------------
__device__ __forceinline__ unsigned long long pack2(float lo, float hi) {
    unsigned long long r;
    asm("mov.b64 %0, {%1, %2};" : "=l"(r) : "f"(lo), "f"(hi));
    return r;
}
__device__ __forceinline__ void fma2(unsigned long long& d, unsigned long long a,
                                     unsigned long long b) {
    asm("fma.rn.f32x2 %0, %1, %2, %0;" : "+l"(d) : "l"(a), "l"(b));
}
__device__ __forceinline__ void unpack2(unsigned long long v, float& lo, float& hi) {
    asm("mov.b64 {%0, %1}, %2;" : "=f"(lo), "=f"(hi) : "l"(v));
}

// ---------------------------------------------------------------------------
// Detect whether edges are int64 (odd 32-bit words all zero) or int32.
// ---------------------------------------------------------------------------
__global__ void detect_kernel(const unsigned int* __restrict__ w) {
    if (threadIdx.x == 0) {
        bool z = true;
#pragma unroll
        for (int i = 1; i < 16; i += 2) z = z && (w[i] == 0u);
        g_is64 = z ? 1 : 0;
    }
}

// ---------------------------------------------------------------------------
// Fused node embedding:  q[n] = sum_j relu(feat[n,:] @ Wemb[:,j] + bemb[j]) * wc[j]
// 128x64 tile, BK=32, 8(M)x4(N) per thread via fma.rn.f32x2, register
// double-buffered global loads. Also zeroes the degree accumulators.
// ---------------------------------------------------------------------------
__global__ __launch_bounds__(256, 2) void embed_kernel(
    const float* __restrict__ feat, const float* __restrict__ Wemb,
    const float* __restrict__ bemb, const float* __restrict__ Wedge) {
    constexpr int BM = 128, BK = 32, LDA = BM + 2;
    __shared__ __align__(16) float As[BK][LDA];   // transposed: As[k][m]
    __shared__ __align__(16) float Bs[BK][HID];

    const int tid = threadIdx.x;
    const int tx = tid & 15;   // hidden group: 4 cols each
    const int ty = tid >> 4;   // node group: 8 rows each
    const int row0 = blockIdx.x * BM;

    // zero packed degree accumulators for this block's nodes
    if (tid < BM) {
        int n = row0 + tid;
        if (n < N_NODES) { g_acc_out[n] = 0ull; g_acc_in[n] = 0ull; }
    }

    // per-thread load coordinates
    int am[4], ak4[4];
    const float* aptr[4];
    bool aval[4];
#pragma unroll
    for (int l = 0; l < 4; l++) {
        int idx = tid + l * 256;
        am[l] = idx >> 3;          // node within tile
        ak4[l] = idx & 7;          // float4 within k-tile
        int node = row0 + am[l];
        aval[l] = node < N_NODES;
        aptr[l] = feat + (size_t)(aval[l] ? node : 0) * IN_DIM + ak4[l] * 4;
    }
    int br[2], bc[2];
#pragma unroll
    for (int l = 0; l < 2; l++) {
        int idx = tid + l * 256;
        br[l] = idx >> 4;
        bc[l] = idx & 15;
    }

    unsigned long long acc2[4][4];
#pragma unroll
    for (int p = 0; p < 4; p++)
#pragma unroll
        for (int j = 0; j < 4; j++) acc2[p][j] = 0ull;

    float4 ra[4], rb[2];
    // prologue loads (k0 = 0)
#pragma unroll
    for (int l = 0; l < 4; l++)
        ra[l] = aval[l] ? *(const float4*)(aptr[l]) : make_float4(0.f, 0.f, 0.f, 0.f);
#pragma unroll
    for (int l = 0; l < 2; l++)
        rb[l] = *(const float4*)&Wemb[(size_t)br[l] * HID + bc[l] * 4];

    constexpr int NT = IN_DIM / BK;  // 8
#pragma unroll 1
    for (int t = 0; t < NT; t++) {
        // stage registers -> smem
#pragma unroll
        for (int l = 0; l < 4; l++) {
            As[ak4[l] * 4 + 0][am[l]] = ra[l].x;
            As[ak4[l] * 4 + 1][am[l]] = ra[l].y;
            As[ak4[l] * 4 + 2][am[l]] = ra[l].z;
            As[ak4[l] * 4 + 3][am[l]] = ra[l].w;
        }
#pragma unroll
        for (int l = 0; l < 2; l++) *(float4*)&Bs[br[l]][bc[l] * 4] = rb[l];
        __syncthreads();

        // issue next tile's loads (overlap with compute below)
        if (t + 1 < NT) {
            int k0 = (t + 1) * BK;
#pragma unroll
            for (int l = 0; l < 4; l++)
                ra[l] = aval[l] ? *(const float4*)(aptr[l] + k0)
                                : make_float4(0.f, 0.f, 0.f, 0.f);
#pragma unroll
            for (int l = 0; l < 2; l++)
                rb[l] = *(const float4*)&Wemb[(size_t)(k0 + br[l]) * HID + bc[l] * 4];
        }

#pragma unroll
        for (int kk = 0; kk < BK; kk++) {
            unsigned long long a2[4];
#pragma unroll
            for (int p = 0; p < 4; p++)
                a2[p] = *(const unsigned long long*)&As[kk][ty * 8 + p * 2];
            float4 bv = *(const float4*)&Bs[kk][tx * 4];
            unsigned long long b2[4];
            b2[0] = pack2(bv.x, bv.x);
            b2[1] = pack2(bv.y, bv.y);
            b2[2] = pack2(bv.z, bv.z);
            b2[3] = pack2(bv.w, bv.w);
#pragma unroll
            for (int p = 0; p < 4; p++)
#pragma unroll
                for (int j = 0; j < 4; j++) fma2(acc2[p][j], a2[p], b2[j]);
        }
        __syncthreads();
    }

    // epilogue: bias + relu + dot with wc, reduce across 16 tx lanes
    float bb[4], wc[4];
#pragma unroll
    for (int j = 0; j < 4; j++) {
        int n = tx * 4 + j;
        bb[j] = bemb[n];
        wc[j] = Wedge[n] + Wedge[HID + n];
    }
#pragma unroll
    for (int p = 0; p < 4; p++) {
        float alo[4], ahi[4];
#pragma unroll
        for (int j = 0; j < 4; j++) unpack2(acc2[p][j], alo[j], ahi[j]);
#pragma unroll
        for (int half = 0; half < 2; half++) {
            float s = 0.f;
#pragma unroll
            for (int j = 0; j < 4; j++) {
                float h = (half ? ahi[j] : alo[j]) + bb[j];
                h = fmaxf(h, 0.f);
                s = fmaf(h, wc[j], s);
            }
#pragma unroll
            for (int off = 1; off < 16; off <<= 1)
                s += __shfl_xor_sync(0xffffffffu, s, off, 16);
            if (tx == 0) {
                int node = row0 + ty * 8 + p * 2 + half;
                if (node < N_NODES) g_q[node] = s;
            }
        }
    }
}

// ---------------------------------------------------------------------------
// Edge pass 1 (2 edges/thread): gumbel-sigmoid weights, int32 edge scratch,
// ONE packed 64-bit atomic per endpoint (count + fixed-point sum of wlp).
// ---------------------------------------------------------------------------
__device__ __forceinline__ float edge_w(float q_s, float q_d, float u, float be) {
    float raw = 0.5f * (q_s + q_d) + be;
    float eps = fmaf(2.0f * BIASF - 1.0f, u, 1.0f - BIASF);
    float gate = logf(eps) - log1pf(-eps);
    float x = gate + raw;  // TEMP = 1
    return 1.0f / (1.0f + expf(-x));
}

__global__ __launch_bounds__(256) void edge_weights_kernel(
    const void* __restrict__ edges, const float* __restrict__ noise,
    const float* __restrict__ b_edge_p, float* __restrict__ out) {
    int t = blockIdx.x * blockDim.x + threadIdx.x;
    if (t * 2 >= N_EDGES) return;

    int s0, s1, d0, d1;
    if (g_is64) {
        longlong2 sv = ((const longlong2*)edges)[t];
        longlong2 dv = ((const longlong2*)((const long long*)edges + N_EDGES))[t];
        s0 = (int)sv.x; s1 = (int)sv.y; d0 = (int)dv.x; d1 = (int)dv.y;
    } else {
        int2 sv = ((const int2*)edges)[t];
        int2 dv = ((const int2*)((const int*)edges + N_EDGES))[t];
        s0 = sv.x; s1 = sv.y; d0 = dv.x; d1 = dv.y;
    }
    ((int2*)g_src)[t] = make_int2(s0, s1);
    ((int2*)g_dst)[t] = make_int2(d0, d1);

    float2 u = ((const float2*)noise)[t];
    float be = *b_edge_p;
    float w0 = edge_w(g_q[s0], g_q[d0], u.x, be);
    float w1 = edge_w(g_q[s1], g_q[d1], u.y, be);

    ((float2*)(out + OFF_WLP))[t] = make_float2(w0, w1);
    ((float2*)(out + OFF_WHP))[t] = make_float2(1.0f - w0, 1.0f - w1);

    unsigned long long e0 = (1ULL << CNT_SHIFT) | (unsigned long long)(w0 * SUM_SCALE);
    unsigned long long e1 = (1ULL << CNT_SHIFT) | (unsigned long long)(w1 * SUM_SCALE);
    atomicAdd(&g_acc_out[s0], e0);
    atomicAdd(&g_acc_in[d0], e0);
    atomicAdd(&g_acc_out[s1], e1);
    atomicAdd(&g_acc_in[d1], e1);
}

// ---------------------------------------------------------------------------
// Node pass: decode packed degrees, precompute rsqrt factors, self-loop outputs
// ---------------------------------------------------------------------------
__global__ __launch_bounds__(256) void node_kernel(float* __restrict__ out) {
    int n = blockIdx.x * blockDim.x + threadIdx.x;
    if (n >= N_NODES) return;
    unsigned long long vo = g_acc_out[n], vi = g_acc_in[n];
    float co = (float)(vo >> CNT_SHIFT);
    float So = (float)(vo & SUM_MASK) * SUM_INV;
    float ci = (float)(vi >> CNT_SHIFT);
    float Si = (float)(vi & SUM_MASK) * SUM_INV;
    // deg = 1 (self loop) + sum over incident edges (EOS terms vanish in fp32)
    float2 ro = make_float2(rsqrtf(1.0f + So), rsqrtf(1.0f + co - So));
    float2 ri = make_float2(rsqrtf(1.0f + Si), rsqrtf(1.0f + ci - Si));
    g_ro[n] = ro;
    g_ri[n] = ri;
    out[OFF_LPN + N_EDGES + n] = (1.0f + EOSF) * ro.x * ri.x;
    out[OFF_HPN + N_EDGES + n] = 1.0f;  // hp self-loop forced to 1
}

// ---------------------------------------------------------------------------
// Edge pass 2 (2 edges/thread): normalize with precomputed float2 factors
// ---------------------------------------------------------------------------
__global__ __launch_bounds__(256) void edge_norm_kernel(float* __restrict__ out) {
    int t = blockIdx.x * blockDim.x + threadIdx.x;
    if (t * 2 >= N_EDGES) return;
    int2 s = ((const int2*)g_src)[t];
    int2 d = ((const int2*)g_dst)[t];
    float2 wl = ((const float2*)(out + OFF_WLP))[t];
    float2 wh = ((const float2*)(out + OFF_WHP))[t];
    float2 ro0 = g_ro[s.x], ro1 = g_ro[s.y];
    float2 ri0 = g_ri[d.x], ri1 = g_ri[d.y];
    ((float2*)(out + OFF_LPN))[t] =
        make_float2((wl.x + EOSF) * ro0.x * ri0.x, (wl.y + EOSF) * ro1.x * ri1.x);
    ((float2*)(out + OFF_HPN))[t] =
        make_float2(-ALPHA * (wh.x + EOSF) * ro0.y * ri0.y,
                    -ALPHA * (wh.y + EOSF) * ro1.y * ri1.y);
}

// ---------------------------------------------------------------------------
extern "C" void kernel_launch(void* const* d_in, const int* in_sizes, int n_in,
                              void* d_out, int out_size) {
    const float* features = (const float*)d_in[0];
    const void*  edges    = d_in[1];
    const float* noise    = (const float*)d_in[2];
    const float* Wemb     = (const float*)d_in[3];
    const float* bemb     = (const float*)d_in[4];
    const float* Wedge    = (const float*)d_in[5];
    const float* bedge    = (const float*)d_in[6];
    float* out = (float*)d_out;

    const int ET = N_EDGES / 2;  // 2 edges per thread
    detect_kernel<<<1, 32>>>((const unsigned int*)edges);
    embed_kernel<<<(N_NODES + 127) / 128, 256>>>(features, Wemb, bemb, Wedge);
    edge_weights_kernel<<<(ET + 255) / 256, 256>>>(edges, noise, bedge, out);
    node_kernel<<<(N_NODES + 255) / 256, 256>>>(out);
    edge_norm_kernel<<<(ET + 255) / 256, 256>>>(out);
}

// round 7
// speedup vs baseline: 1.0086x; 1.0061x over previous
#include <cuda_runtime.h>
#include <cuda_bf16.h>
#include <mma.h>
#include <cstdint>
#include <math.h>

using namespace nvcuda;

#define N_NODES 100000
#define N_EDGES 1600000
#define IN_DIM 256
#define HID 64
#define ALPHA 0.1f
#define EOSF 1e-10f
#define BIASF 1e-4f

// output layout: [w_lp_norm (E+N)] [w_hp_norm (E+N)] [weights_lp (E)] [weights_hp (E)]
#define OFF_LPN 0
#define OFF_HPN (N_EDGES + N_NODES)
#define OFF_WLP (2 * (N_EDGES + N_NODES))
#define OFF_WHP (2 * (N_EDGES + N_NODES) + N_EDGES)

// fixed-point packed degree accumulator: count at bit 44, sum(wlp)*2^32 in low 44 bits
#define CNT_SHIFT 44
#define SUM_MASK ((1ULL << CNT_SHIFT) - 1ULL)
#define SUM_SCALE 4294967296.0f
#define SUM_INV (1.0f / 4294967296.0f)

// scratch (no allocations allowed)
__device__ float g_q[N_NODES];
__device__ unsigned long long g_acc_out[N_NODES];
__device__ unsigned long long g_acc_in[N_NODES];
__device__ __align__(16) float2 g_ro[N_NODES];
__device__ __align__(16) float2 g_ri[N_NODES];
__device__ __align__(16) int g_src[N_EDGES];
__device__ __align__(16) int g_dst[N_EDGES];
__device__ int g_is64;
// bf16 hi/lo images of W_emb, row-major [IN_DIM][HID]
__device__ __align__(16) __nv_bfloat16 g_Bh[IN_DIM * HID];
__device__ __align__(16) __nv_bfloat16 g_Bl[IN_DIM * HID];

// ---------------------------------------------------------------------------
// Prep: int64-vs-int32 edge detect + bf16 hi/lo split of W_emb
// ---------------------------------------------------------------------------
__global__ void prep_kernel(const unsigned int* __restrict__ edges_w,
                            const float* __restrict__ Wemb) {
    int idx = blockIdx.x * 256 + threadIdx.x;  // 0..16383
    if (blockIdx.x == 0 && threadIdx.x == 0) {
        bool z = true;
#pragma unroll
        for (int i = 1; i < 16; i += 2) z = z && (edges_w[i] == 0u);
        g_is64 = z ? 1 : 0;
    }
    if (idx < IN_DIM * HID) {
        float w = Wemb[idx];
        __nv_bfloat16 h = __float2bfloat16(w);
        __nv_bfloat16 l = __float2bfloat16(w - __bfloat162float(h));
        g_Bh[idx] = h;
        g_Bl[idx] = l;
    }
}

// ---------------------------------------------------------------------------
// Embed via HMMA (wmma bf16, 3-term split, fp32 accum):
//   q[n] = sum_j relu((feat @ W)[n,j] + b[j]) * wc[j]
// Per-CTA: 128 nodes x 64 hid; K in 2 chunks of 128.
// smem: Ah[128][136] | Al[128][136] | Bh[128][72] | Bl[128][72]  (bf16)
// Epilogue: acc -> smem fp32 [128][68], relu-dot reduce -> g_q.
// ---------------------------------------------------------------------------
#define LDA_S 136
#define LDB_S 72
#define LDD_S 68
#define SM_AH 0
#define SM_AL (128 * LDA_S)                 // bf16 elements
#define SM_BH (2 * 128 * LDA_S)
#define SM_BL (2 * 128 * LDA_S + 128 * LDB_S)
#define EMBED_SMEM_BYTES ((2 * 128 * LDA_S + 2 * 128 * LDB_S) * 2)

__global__ __launch_bounds__(256) void embed_kernel(const float* __restrict__ feat,
                                                    const float* __restrict__ bemb,
                                                    const float* __restrict__ Wedge) {
    extern __shared__ __nv_bfloat16 sm[];
    __shared__ float s_b[HID], s_wc[HID];

    const int tid = threadIdx.x, wid = tid >> 5;
    const int row0 = blockIdx.x * 128;

    if (tid < HID) {
        s_b[tid] = bemb[tid];
        s_wc[tid] = Wedge[tid] + Wedge[HID + tid];
    }
    if (tid < 128) {
        int n = row0 + tid;
        if (n < N_NODES) { g_acc_out[n] = 0ull; g_acc_in[n] = 0ull; }
    }

    wmma::fragment<wmma::accumulator, 16, 16, 16, float> acc[4];
#pragma unroll
    for (int nt = 0; nt < 4; nt++) wmma::fill_fragment(acc[nt], 0.0f);

    const int m0 = wid * 16;

#pragma unroll 1
    for (int c = 0; c < 2; c++) {
        if (c) __syncthreads();  // previous chunk's mma reads done before overwrite

        // A chunk: 128 nodes x 128 K fp32 -> bf16 hi/lo
#pragma unroll
        for (int i = 0; i < 16; i++) {
            int idx = tid + i * 256;          // float4 index 0..4095
            int m = idx >> 5, k = (idx & 31) * 4;
            int node = row0 + m;
            float4 v = make_float4(0.f, 0.f, 0.f, 0.f);
            if (node < N_NODES)
                v = *(const float4*)&feat[(size_t)node * IN_DIM + c * 128 + k];
            __nv_bfloat162 h01 = __floats2bfloat162_rn(v.x, v.y);
            __nv_bfloat162 h23 = __floats2bfloat162_rn(v.z, v.w);
            float2 f01 = __bfloat1622float2(h01);
            float2 f23 = __bfloat1622float2(h23);
            __nv_bfloat162 l01 = __floats2bfloat162_rn(v.x - f01.x, v.y - f01.y);
            __nv_bfloat162 l23 = __floats2bfloat162_rn(v.z - f23.x, v.w - f23.y);
            uint2 hw, lw;
            hw.x = *(uint32_t*)&h01; hw.y = *(uint32_t*)&h23;
            lw.x = *(uint32_t*)&l01; lw.y = *(uint32_t*)&l23;
            *(uint2*)&sm[SM_AH + m * LDA_S + k] = hw;
            *(uint2*)&sm[SM_AL + m * LDA_S + k] = lw;
        }
        // B chunk: 128 rows x 64 cols bf16 = 1024 uint4 per image
#pragma unroll
        for (int i = 0; i < 4; i++) {
            int idx = tid + i * 256;          // uint4 (8 bf16) index 0..1023
            int r = idx >> 3, c8 = (idx & 7) * 8;
            *(uint4*)&sm[SM_BH + r * LDB_S + c8] =
                *(const uint4*)&g_Bh[(c * 128 + r) * HID + c8];
            *(uint4*)&sm[SM_BL + r * LDB_S + c8] =
                *(const uint4*)&g_Bl[(c * 128 + r) * HID + c8];
        }
        __syncthreads();

#pragma unroll
        for (int kt = 0; kt < 8; kt++) {
            wmma::fragment<wmma::matrix_a, 16, 16, 16, __nv_bfloat16, wmma::row_major> ah, al;
            wmma::load_matrix_sync(ah, &sm[SM_AH + m0 * LDA_S + kt * 16], LDA_S);
            wmma::load_matrix_sync(al, &sm[SM_AL + m0 * LDA_S + kt * 16], LDA_S);
#pragma unroll
            for (int nt = 0; nt < 4; nt++) {
                wmma::fragment<wmma::matrix_b, 16, 16, 16, __nv_bfloat16, wmma::row_major> bh, bl;
                wmma::load_matrix_sync(bh, &sm[SM_BH + kt * 16 * LDB_S + nt * 16], LDB_S);
                wmma::load_matrix_sync(bl, &sm[SM_BL + kt * 16 * LDB_S + nt * 16], LDB_S);
                wmma::mma_sync(acc[nt], ah, bh, acc[nt]);
                wmma::mma_sync(acc[nt], al, bh, acc[nt]);
                wmma::mma_sync(acc[nt], ah, bl, acc[nt]);
            }
        }
    }
    __syncthreads();

    // store accumulators to smem fp32 [128][68]
    float* Ds = (float*)sm;
#pragma unroll
    for (int nt = 0; nt < 4; nt++)
        wmma::store_matrix_sync(&Ds[m0 * LDD_S + nt * 16], acc[nt], LDD_S,
                                wmma::mem_row_major);
    __syncthreads();

    // reduce: relu(D + b) . wc per node (diagonal column order)
    if (tid < 128) {
        int node = row0 + tid;
        float s = 0.f;
#pragma unroll
        for (int j = 0; j < HID; j++) {
            int jj = (j + tid) & (HID - 1);
            float h = Ds[tid * LDD_S + jj] + s_b[jj];
            s = fmaf(fmaxf(h, 0.f), s_wc[jj], s);
        }
        if (node < N_NODES) g_q[node] = s;
    }
}

// ---------------------------------------------------------------------------
// Edge pass 1 (2 edges/thread): gumbel-sigmoid weights, int32 edge scratch,
// ONE packed 64-bit atomic per endpoint.
// ---------------------------------------------------------------------------
__device__ __forceinline__ float edge_w(float q_s, float q_d, float u, float be) {
    float raw = 0.5f * (q_s + q_d) + be;
    float eps = fmaf(2.0f * BIASF - 1.0f, u, 1.0f - BIASF);
    float gate = logf(eps) - log1pf(-eps);
    float x = gate + raw;  // TEMP = 1
    return 1.0f / (1.0f + expf(-x));
}

__global__ __launch_bounds__(256) void edge_weights_kernel(
    const void* __restrict__ edges, const float* __restrict__ noise,
    const float* __restrict__ b_edge_p, float* __restrict__ out) {
    int t = blockIdx.x * blockDim.x + threadIdx.x;
    if (t * 2 >= N_EDGES) return;

    int s0, s1, d0, d1;
    if (g_is64) {
        longlong2 sv = ((const longlong2*)edges)[t];
        longlong2 dv = ((const longlong2*)((const long long*)edges + N_EDGES))[t];
        s0 = (int)sv.x; s1 = (int)sv.y; d0 = (int)dv.x; d1 = (int)dv.y;
    } else {
        int2 sv = ((const int2*)edges)[t];
        int2 dv = ((const int2*)((const int*)edges + N_EDGES))[t];
        s0 = sv.x; s1 = sv.y; d0 = dv.x; d1 = dv.y;
    }
    ((int2*)g_src)[t] = make_int2(s0, s1);
    ((int2*)g_dst)[t] = make_int2(d0, d1);

    float2 u = ((const float2*)noise)[t];
    float be = *b_edge_p;
    float w0 = edge_w(g_q[s0], g_q[d0], u.x, be);
    float w1 = edge_w(g_q[s1], g_q[d1], u.y, be);

    ((float2*)(out + OFF_WLP))[t] = make_float2(w0, w1);
    ((float2*)(out + OFF_WHP))[t] = make_float2(1.0f - w0, 1.0f - w1);

    unsigned long long e0 = (1ULL << CNT_SHIFT) | (unsigned long long)(w0 * SUM_SCALE);
    unsigned long long e1 = (1ULL << CNT_SHIFT) | (unsigned long long)(w1 * SUM_SCALE);
    atomicAdd(&g_acc_out[s0], e0);
    atomicAdd(&g_acc_in[d0], e0);
    atomicAdd(&g_acc_out[s1], e1);
    atomicAdd(&g_acc_in[d1], e1);
}

// ---------------------------------------------------------------------------
// Node pass: decode packed degrees, precompute rsqrt factors, self-loop outputs
// ---------------------------------------------------------------------------
__global__ __launch_bounds__(256) void node_kernel(float* __restrict__ out) {
    int n = blockIdx.x * blockDim.x + threadIdx.x;
    if (n >= N_NODES) return;
    unsigned long long vo = g_acc_out[n], vi = g_acc_in[n];
    float co = (float)(vo >> CNT_SHIFT);
    float So = (float)(vo & SUM_MASK) * SUM_INV;
    float ci = (float)(vi >> CNT_SHIFT);
    float Si = (float)(vi & SUM_MASK) * SUM_INV;
    float2 ro = make_float2(rsqrtf(1.0f + So), rsqrtf(1.0f + co - So));
    float2 ri = make_float2(rsqrtf(1.0f + Si), rsqrtf(1.0f + ci - Si));
    g_ro[n] = ro;
    g_ri[n] = ri;
    out[OFF_LPN + N_EDGES + n] = (1.0f + EOSF) * ro.x * ri.x;
    out[OFF_HPN + N_EDGES + n] = 1.0f;
}

// ---------------------------------------------------------------------------
// Edge pass 2 (2 edges/thread): normalize with precomputed float2 factors
// ---------------------------------------------------------------------------
__global__ __launch_bounds__(256) void edge_norm_kernel(float* __restrict__ out) {
    int t = blockIdx.x * blockDim.x + threadIdx.x;
    if (t * 2 >= N_EDGES) return;
    int2 s = ((const int2*)g_src)[t];
    int2 d = ((const int2*)g_dst)[t];
    float2 wl = ((const float2*)(out + OFF_WLP))[t];
    float2 wh = ((const float2*)(out + OFF_WHP))[t];
    float2 ro0 = g_ro[s.x], ro1 = g_ro[s.y];
    float2 ri0 = g_ri[d.x], ri1 = g_ri[d.y];
    ((float2*)(out + OFF_LPN))[t] =
        make_float2((wl.x + EOSF) * ro0.x * ri0.x, (wl.y + EOSF) * ro1.x * ri1.x);
    ((float2*)(out + OFF_HPN))[t] =
        make_float2(-ALPHA * (wh.x + EOSF) * ro0.y * ri0.y,
                    -ALPHA * (wh.y + EOSF) * ro1.y * ri1.y);
}

// ---------------------------------------------------------------------------
extern "C" void kernel_launch(void* const* d_in, const int* in_sizes, int n_in,
                              void* d_out, int out_size) {
    const float* features = (const float*)d_in[0];
    const void*  edges    = d_in[1];
    const float* noise    = (const float*)d_in[2];
    const float* Wemb     = (const float*)d_in[3];
    const float* bemb     = (const float*)d_in[4];
    const float* Wedge    = (const float*)d_in[5];
    const float* bedge    = (const float*)d_in[6];
    float* out = (float*)d_out;

    // not a stream op: executes immediately, identical on every call
    cudaFuncSetAttribute(embed_kernel, cudaFuncAttributeMaxDynamicSharedMemorySize,
                         EMBED_SMEM_BYTES);

    const int ET = N_EDGES / 2;
    prep_kernel<<<64, 256>>>((const unsigned int*)edges, Wemb);
    embed_kernel<<<(N_NODES + 127) / 128, 256, EMBED_SMEM_BYTES>>>(features, bemb, Wedge);
    edge_weights_kernel<<<(ET + 255) / 256, 256>>>(edges, noise, bedge, out);
    node_kernel<<<(N_NODES + 255) / 256, 256>>>(out);
    edge_norm_kernel<<<(ET + 255) / 256, 256>>>(out);
}

// round 8
// speedup vs baseline: 1.1478x; 1.1380x over previous
#include <cuda_runtime.h>
#include <cuda_bf16.h>
#include <mma.h>
#include <cstdint>
#include <math.h>

using namespace nvcuda;

#define N_NODES 100000
#define N_EDGES 1600000
#define IN_DIM 256
#define HID 64
#define ALPHA 0.1f
#define EOSF 1e-10f
#define BIASF 1e-4f

// output layout: [w_lp_norm (E+N)] [w_hp_norm (E+N)] [weights_lp (E)] [weights_hp (E)]
#define OFF_LPN 0
#define OFF_HPN (N_EDGES + N_NODES)
#define OFF_WLP (2 * (N_EDGES + N_NODES))
#define OFF_WHP (2 * (N_EDGES + N_NODES) + N_EDGES)

// fixed-point packed degree accumulator: count at bit 44, sum(wlp)*2^32 in low 44 bits
#define CNT_SHIFT 44
#define SUM_MASK ((1ULL << CNT_SHIFT) - 1ULL)
#define SUM_SCALE 4294967296.0f
#define SUM_INV (1.0f / 4294967296.0f)

// scratch (no allocations allowed)
__device__ float g_q[N_NODES];
__device__ unsigned long long g_acc_out[N_NODES];
__device__ unsigned long long g_acc_in[N_NODES];
__device__ __align__(16) float2 g_ro[N_NODES];
__device__ __align__(16) float2 g_ri[N_NODES];
__device__ __align__(16) int g_src[N_EDGES];
__device__ __align__(16) int g_dst[N_EDGES];
__device__ int g_is64;
// bf16 hi/lo images of W_emb, row-major [IN_DIM][HID]
__device__ __align__(16) __nv_bfloat16 g_Bh[IN_DIM * HID];
__device__ __align__(16) __nv_bfloat16 g_Bl[IN_DIM * HID];

// ---------------------------------------------------------------------------
// Prep: int64-vs-int32 edge detect + bf16 hi/lo split of W_emb
// ---------------------------------------------------------------------------
__global__ void prep_kernel(const unsigned int* __restrict__ edges_w,
                            const float* __restrict__ Wemb) {
    int idx = blockIdx.x * 256 + threadIdx.x;  // 0..16383
    if (blockIdx.x == 0 && threadIdx.x == 0) {
        bool z = true;
#pragma unroll
        for (int i = 1; i < 16; i += 2) z = z && (edges_w[i] == 0u);
        g_is64 = z ? 1 : 0;
    }
    if (idx < IN_DIM * HID) {
        float w = Wemb[idx];
        __nv_bfloat16 h = __float2bfloat16(w);
        __nv_bfloat16 l = __float2bfloat16(w - __bfloat162float(h));
        g_Bh[idx] = h;
        g_Bl[idx] = l;
    }
}

// ---------------------------------------------------------------------------
// Embed via HMMA (wmma bf16, 3-term split, fp32 accum):
//   q[n] = sum_j relu((feat @ W)[n,j] + b[j]) * wc[j]
// Per-CTA: 128 nodes x 64 hid; K in 4 chunks of 64 (small chunks + 3 CTAs/SM
// -> cross-CTA overlap of load/convert with MMA).
// smem: Ah[128][72] | Al[128][72] | Bh[64][72] | Bl[64][72]  (bf16) = 55.3KB
// ---------------------------------------------------------------------------
#define LDA_S 72
#define LDB_S 72
#define LDD_S 68
#define SM_AH 0
#define SM_AL (128 * LDA_S)
#define SM_BH (2 * 128 * LDA_S)
#define SM_BL (2 * 128 * LDA_S + 64 * LDB_S)
#define EMBED_SMEM_BYTES ((2 * 128 * LDA_S + 2 * 64 * LDB_S) * 2)

__global__ __launch_bounds__(256, 3) void embed_kernel(const float* __restrict__ feat,
                                                       const float* __restrict__ bemb,
                                                       const float* __restrict__ Wedge) {
    extern __shared__ __nv_bfloat16 sm[];
    __shared__ float s_b[HID], s_wc[HID];

    const int tid = threadIdx.x, wid = tid >> 5;
    const int row0 = blockIdx.x * 128;

    if (tid < HID) {
        s_b[tid] = bemb[tid];
        s_wc[tid] = Wedge[tid] + Wedge[HID + tid];
    }
    if (tid < 128) {
        int n = row0 + tid;
        if (n < N_NODES) { g_acc_out[n] = 0ull; g_acc_in[n] = 0ull; }
    }

    wmma::fragment<wmma::accumulator, 16, 16, 16, float> acc[4];
#pragma unroll
    for (int nt = 0; nt < 4; nt++) wmma::fill_fragment(acc[nt], 0.0f);

    const int m0 = wid * 16;

#pragma unroll 1
    for (int c = 0; c < 4; c++) {
        if (c) __syncthreads();  // previous chunk's mma reads done before overwrite

        // A chunk: 128 nodes x 64 K fp32 -> bf16 hi/lo (8 float4 per thread)
#pragma unroll
        for (int i = 0; i < 8; i++) {
            int idx = tid + i * 256;          // float4 index 0..2047
            int m = idx >> 4, k = (idx & 15) * 4;
            int node = row0 + m;
            float4 v = make_float4(0.f, 0.f, 0.f, 0.f);
            if (node < N_NODES)
                v = *(const float4*)&feat[(size_t)node * IN_DIM + c * 64 + k];
            __nv_bfloat162 h01 = __floats2bfloat162_rn(v.x, v.y);
            __nv_bfloat162 h23 = __floats2bfloat162_rn(v.z, v.w);
            float2 f01 = __bfloat1622float2(h01);
            float2 f23 = __bfloat1622float2(h23);
            __nv_bfloat162 l01 = __floats2bfloat162_rn(v.x - f01.x, v.y - f01.y);
            __nv_bfloat162 l23 = __floats2bfloat162_rn(v.z - f23.x, v.w - f23.y);
            uint2 hw, lw;
            hw.x = *(uint32_t*)&h01; hw.y = *(uint32_t*)&h23;
            lw.x = *(uint32_t*)&l01; lw.y = *(uint32_t*)&l23;
            *(uint2*)&sm[SM_AH + m * LDA_S + k] = hw;
            *(uint2*)&sm[SM_AL + m * LDA_S + k] = lw;
        }
        // B chunk: 64 rows x 64 cols bf16 = 512 uint4 per image
#pragma unroll
        for (int i = 0; i < 2; i++) {
            int idx = tid + i * 256;          // uint4 index 0..511
            int r = idx >> 3, c8 = (idx & 7) * 8;
            *(uint4*)&sm[SM_BH + r * LDB_S + c8] =
                *(const uint4*)&g_Bh[(c * 64 + r) * HID + c8];
            *(uint4*)&sm[SM_BL + r * LDB_S + c8] =
                *(const uint4*)&g_Bl[(c * 64 + r) * HID + c8];
        }
        __syncthreads();

#pragma unroll
        for (int kt = 0; kt < 4; kt++) {
            wmma::fragment<wmma::matrix_a, 16, 16, 16, __nv_bfloat16, wmma::row_major> ah, al;
            wmma::load_matrix_sync(ah, &sm[SM_AH + m0 * LDA_S + kt * 16], LDA_S);
            wmma::load_matrix_sync(al, &sm[SM_AL + m0 * LDA_S + kt * 16], LDA_S);
#pragma unroll
            for (int nt = 0; nt < 4; nt++) {
                wmma::fragment<wmma::matrix_b, 16, 16, 16, __nv_bfloat16, wmma::row_major> bh, bl;
                wmma::load_matrix_sync(bh, &sm[SM_BH + kt * 16 * LDB_S + nt * 16], LDB_S);
                wmma::load_matrix_sync(bl, &sm[SM_BL + kt * 16 * LDB_S + nt * 16], LDB_S);
                wmma::mma_sync(acc[nt], ah, bh, acc[nt]);
                wmma::mma_sync(acc[nt], al, bh, acc[nt]);
                wmma::mma_sync(acc[nt], ah, bl, acc[nt]);
            }
        }
    }
    __syncthreads();

    // store accumulators to smem fp32 [128][68]
    float* Ds = (float*)sm;
#pragma unroll
    for (int nt = 0; nt < 4; nt++)
        wmma::store_matrix_sync(&Ds[m0 * LDD_S + nt * 16], acc[nt], LDD_S,
                                wmma::mem_row_major);
    __syncthreads();

    // reduce: relu(D + b) . wc per node (diagonal column order)
    if (tid < 128) {
        int node = row0 + tid;
        float s = 0.f;
#pragma unroll
        for (int j = 0; j < HID; j++) {
            int jj = (j + tid) & (HID - 1);
            float h = Ds[tid * LDD_S + jj] + s_b[jj];
            s = fmaf(fmaxf(h, 0.f), s_wc[jj], s);
        }
        if (node < N_NODES) g_q[node] = s;
    }
}

// ---------------------------------------------------------------------------
// Edge pass 1 (4 edges/thread): gumbel-sigmoid weights, ONE packed 64-bit
// atomic per endpoint. Streaming traffic uses .cs hints so L1 keeps g_q.
// ---------------------------------------------------------------------------
__device__ __forceinline__ float edge_w(float q_s, float q_d, float u, float be) {
    float raw = 0.5f * (q_s + q_d) + be;
    float eps = fmaf(2.0f * BIASF - 1.0f, u, 1.0f - BIASF);
    float gate = logf(eps) - log1pf(-eps);
    float x = gate + raw;  // TEMP = 1
    return 1.0f / (1.0f + expf(-x));
}

__global__ __launch_bounds__(256) void edge_weights_kernel(
    const void* __restrict__ edges, const float* __restrict__ noise,
    const float* __restrict__ b_edge_p, float* __restrict__ out) {
    int t = blockIdx.x * blockDim.x + threadIdx.x;
    if (t * 4 >= N_EDGES) return;
    const int is64 = g_is64;

    int s[4], d[4];
    if (is64) {
        const longlong2* es = (const longlong2*)edges;
        const longlong2* ed = (const longlong2*)((const long long*)edges + N_EDGES);
        longlong2 s01 = __ldcs(&es[t * 2]), s23 = __ldcs(&es[t * 2 + 1]);
        longlong2 d01 = __ldcs(&ed[t * 2]), d23 = __ldcs(&ed[t * 2 + 1]);
        s[0] = (int)s01.x; s[1] = (int)s01.y; s[2] = (int)s23.x; s[3] = (int)s23.y;
        d[0] = (int)d01.x; d[1] = (int)d01.y; d[2] = (int)d23.x; d[3] = (int)d23.y;
        __stcs((int4*)g_src + t, make_int4(s[0], s[1], s[2], s[3]));
        __stcs((int4*)g_dst + t, make_int4(d[0], d[1], d[2], d[3]));
    } else {
        int4 sv = __ldcs((const int4*)edges + t);
        int4 dv = __ldcs((const int4*)((const int*)edges + N_EDGES) + t);
        s[0] = sv.x; s[1] = sv.y; s[2] = sv.z; s[3] = sv.w;
        d[0] = dv.x; d[1] = dv.y; d[2] = dv.z; d[3] = dv.w;
    }

    // issue all 8 gathers before any math (MLP against L2 latency)
    float qs[4], qd[4];
#pragma unroll
    for (int i = 0; i < 4; i++) { qs[i] = g_q[s[i]]; qd[i] = g_q[d[i]]; }

    float4 u = __ldcs((const float4*)noise + t);
    float be = *b_edge_p;
    float w[4];
    w[0] = edge_w(qs[0], qd[0], u.x, be);
    w[1] = edge_w(qs[1], qd[1], u.y, be);
    w[2] = edge_w(qs[2], qd[2], u.z, be);
    w[3] = edge_w(qs[3], qd[3], u.w, be);

    __stcs((float4*)(out + OFF_WLP) + t, make_float4(w[0], w[1], w[2], w[3]));
    __stcs((float4*)(out + OFF_WHP) + t,
           make_float4(1.0f - w[0], 1.0f - w[1], 1.0f - w[2], 1.0f - w[3]));

#pragma unroll
    for (int i = 0; i < 4; i++) {
        unsigned long long e =
            (1ULL << CNT_SHIFT) | (unsigned long long)(w[i] * SUM_SCALE);
        atomicAdd(&g_acc_out[s[i]], e);
        atomicAdd(&g_acc_in[d[i]], e);
    }
}

// ---------------------------------------------------------------------------
// Node pass (2 nodes/thread): decode packed degrees, rsqrt factors, self-loops
// ---------------------------------------------------------------------------
__global__ __launch_bounds__(256) void node_kernel(float* __restrict__ out) {
    int t = blockIdx.x * blockDim.x + threadIdx.x;
    if (t * 2 >= N_NODES) return;
#pragma unroll
    for (int i = 0; i < 2; i++) {
        int n = t * 2 + i;
        unsigned long long vo = g_acc_out[n], vi = g_acc_in[n];
        float co = (float)(vo >> CNT_SHIFT);
        float So = (float)(vo & SUM_MASK) * SUM_INV;
        float ci = (float)(vi >> CNT_SHIFT);
        float Si = (float)(vi & SUM_MASK) * SUM_INV;
        float2 ro = make_float2(rsqrtf(1.0f + So), rsqrtf(1.0f + co - So));
        float2 ri = make_float2(rsqrtf(1.0f + Si), rsqrtf(1.0f + ci - Si));
        g_ro[n] = ro;
        g_ri[n] = ri;
        out[OFF_LPN + N_EDGES + n] = (1.0f + EOSF) * ro.x * ri.x;
        out[OFF_HPN + N_EDGES + n] = 1.0f;
    }
}

// ---------------------------------------------------------------------------
// Edge pass 2 (4 edges/thread): normalize with precomputed float2 factors.
// Reads edges directly when int32 (skips scratch), streams via .cs hints.
// ---------------------------------------------------------------------------
__global__ __launch_bounds__(256) void edge_norm_kernel(const void* __restrict__ edges,
                                                        float* __restrict__ out) {
    int t = blockIdx.x * blockDim.x + threadIdx.x;
    if (t * 4 >= N_EDGES) return;
    int4 s, d;
    if (g_is64) {
        s = __ldcs((const int4*)g_src + t);
        d = __ldcs((const int4*)g_dst + t);
    } else {
        s = __ldcs((const int4*)edges + t);
        d = __ldcs((const int4*)((const int*)edges + N_EDGES) + t);
    }
    // issue all 8 factor gathers first
    float2 ro0 = g_ro[s.x], ro1 = g_ro[s.y], ro2 = g_ro[s.z], ro3 = g_ro[s.w];
    float2 ri0 = g_ri[d.x], ri1 = g_ri[d.y], ri2 = g_ri[d.z], ri3 = g_ri[d.w];
    float4 wl = __ldcs((const float4*)(out + OFF_WLP) + t);
    float4 wh = __ldcs((const float4*)(out + OFF_WHP) + t);
    __stcs((float4*)(out + OFF_LPN) + t,
           make_float4((wl.x + EOSF) * ro0.x * ri0.x, (wl.y + EOSF) * ro1.x * ri1.x,
                       (wl.z + EOSF) * ro2.x * ri2.x, (wl.w + EOSF) * ro3.x * ri3.x));
    __stcs((float4*)(out + OFF_HPN) + t,
           make_float4(-ALPHA * (wh.x + EOSF) * ro0.y * ri0.y,
                       -ALPHA * (wh.y + EOSF) * ro1.y * ri1.y,
                       -ALPHA * (wh.z + EOSF) * ro2.y * ri2.y,
                       -ALPHA * (wh.w + EOSF) * ro3.y * ri3.y));
}

// ---------------------------------------------------------------------------
extern "C" void kernel_launch(void* const* d_in, const int* in_sizes, int n_in,
                              void* d_out, int out_size) {
    const float* features = (const float*)d_in[0];
    const void*  edges    = d_in[1];
    const float* noise    = (const float*)d_in[2];
    const float* Wemb     = (const float*)d_in[3];
    const float* bemb     = (const float*)d_in[4];
    const float* Wedge    = (const float*)d_in[5];
    const float* bedge    = (const float*)d_in[6];
    float* out = (float*)d_out;

    cudaFuncSetAttribute(embed_kernel, cudaFuncAttributeMaxDynamicSharedMemorySize,
                         EMBED_SMEM_BYTES);

    const int ET = N_EDGES / 4;  // 4 edges per thread
    prep_kernel<<<64, 256>>>((const unsigned int*)edges, Wemb);
    embed_kernel<<<(N_NODES + 127) / 128, 256, EMBED_SMEM_BYTES>>>(features, bemb, Wedge);
    edge_weights_kernel<<<(ET + 255) / 256, 256>>>(edges, noise, bedge, out);
    node_kernel<<<(N_NODES / 2 + 255) / 256, 256>>>(out);
    edge_norm_kernel<<<(ET + 255) / 256, 256>>>(edges, out);
}